// round 6
// baseline (speedup 1.0000x reference)
#include <cuda_runtime.h>
#include <cstdint>

// Haar DWT2: input (B=8, C=32, H=512, W=512) fp32
// output (B=8, 4, C=32, 256, 256) fp32, bands LL, LH, HL, HH.
//
// Each thread: 8 output columns (16 input columns) of one output row.
// Loads: 2 rows x 4 float4 (streaming) = 128B. Stores: 4 bands x 2 float4 = 128B.

#define B_DIM 8
#define C_DIM 32
#define H_DIM 512
#define W_DIM 512
#define H2 (H_DIM / 2)      // 256
#define W2 (W_DIM / 2)      // 256
#define WO (W2 / 8)         // 32 octets of output columns per row

__global__ __launch_bounds__(256)
void haar_dwt2_kernel(const float* __restrict__ in, float* __restrict__ out) {
    // total threads = B*C*H2*WO = 8*32*256*32 = 2,097,152
    unsigned t = blockIdx.x * blockDim.x + threadIdx.x;

    unsigned wo = t & (WO - 1);            // 0..31
    unsigned h2 = (t >> 5) & (H2 - 1);     // 0..255
    unsigned c  = (t >> 13) & (C_DIM - 1); // 0..31
    unsigned b  = t >> 18;                 // 0..7

    // input base for (b, c, 2*h2, 16*wo)
    size_t in_base = ((size_t)(b * C_DIM + c) * H_DIM + 2u * h2) * W_DIM + 16u * wo;
    const float4* r0 = (const float4*)(in + in_base);
    const float4* r1 = (const float4*)(in + in_base + W_DIM);

    // Front-batch all 8 loads (streaming hint: evict-first in L2)
    float4 a0 = __ldcs(r0 + 0);
    float4 a1 = __ldcs(r0 + 1);
    float4 a2 = __ldcs(r0 + 2);
    float4 a3 = __ldcs(r0 + 3);
    float4 b0 = __ldcs(r1 + 0);
    float4 b1 = __ldcs(r1 + 1);
    float4 b2 = __ldcs(r1 + 2);
    float4 b3 = __ldcs(r1 + 3);

    float ll[8], lh[8], hl[8], hh[8];

    #define HAAR(i, x00, x01, x10, x11)                      \
        do {                                                  \
            float s0 = (x00) + (x01), s1 = (x10) + (x11);     \
            float d0 = (x00) - (x01), d1 = (x10) - (x11);     \
            ll[i] = (s0 + s1) * 0.5f;                         \
            lh[i] = (s0 - s1) * 0.5f;                         \
            hl[i] = (d0 + d1) * 0.5f;                         \
            hh[i] = (d0 - d1) * 0.5f;                         \
        } while (0)

    HAAR(0, a0.x, a0.y, b0.x, b0.y);
    HAAR(1, a0.z, a0.w, b0.z, b0.w);
    HAAR(2, a1.x, a1.y, b1.x, b1.y);
    HAAR(3, a1.z, a1.w, b1.z, b1.w);
    HAAR(4, a2.x, a2.y, b2.x, b2.y);
    HAAR(5, a2.z, a2.w, b2.z, b2.w);
    HAAR(6, a3.x, a3.y, b3.x, b3.y);
    HAAR(7, a3.z, a3.w, b3.z, b3.w);
    #undef HAAR

    // output layout: [B, 4, C, H2, W2]; per-(b,band,c) plane is H2*W2
    size_t plane = (size_t)H2 * W2;
    size_t ob = ((size_t)(b * 4) * C_DIM + c) * plane + (size_t)h2 * W2 + 8u * wo;
    size_t bandstep = (size_t)C_DIM * plane;

    float4* o_ll = (float4*)(out + ob + 0 * bandstep);
    float4* o_lh = (float4*)(out + ob + 1 * bandstep);
    float4* o_hl = (float4*)(out + ob + 2 * bandstep);
    float4* o_hh = (float4*)(out + ob + 3 * bandstep);

    __stcs(o_ll + 0, make_float4(ll[0], ll[1], ll[2], ll[3]));
    __stcs(o_ll + 1, make_float4(ll[4], ll[5], ll[6], ll[7]));
    __stcs(o_lh + 0, make_float4(lh[0], lh[1], lh[2], lh[3]));
    __stcs(o_lh + 1, make_float4(lh[4], lh[5], lh[6], lh[7]));
    __stcs(o_hl + 0, make_float4(hl[0], hl[1], hl[2], hl[3]));
    __stcs(o_hl + 1, make_float4(hl[4], hl[5], hl[6], hl[7]));
    __stcs(o_hh + 0, make_float4(hh[0], hh[1], hh[2], hh[3]));
    __stcs(o_hh + 1, make_float4(hh[4], hh[5], hh[6], hh[7]));
}

extern "C" void kernel_launch(void* const* d_in, const int* in_sizes, int n_in,
                              void* d_out, int out_size) {
    const float* in = (const float*)d_in[0];
    float* out = (float*)d_out;
    unsigned total = B_DIM * C_DIM * H2 * WO;   // 2,097,152 threads
    haar_dwt2_kernel<<<total / 256, 256>>>(in, out);
}

// round 14
// speedup vs baseline: 1.1495x; 1.1495x over previous
#include <cuda_runtime.h>
#include <cstdint>

// Haar DWT2: input (B=8, C=32, H=512, W=512) fp32
// output (B=8, 4, C=32, 256, 256) fp32, bands LL, LH, HL, HH.
//
// R1 shape (known 82.0us, DRAM 81%): each thread does 4 output columns
// (8 input columns) of one output row. Loads: 2 rows x 2 float4 (default
// policy). Stores: 4 bands x 1 float4 with __stcs (evict-first) — the single
// isolated change vs R1.

#define B_DIM 8
#define C_DIM 32
#define H_DIM 512
#define W_DIM 512
#define H2 (H_DIM / 2)      // 256
#define W2 (W_DIM / 2)      // 256
#define WQ (W2 / 4)         // 64 quads of output columns per row

__global__ __launch_bounds__(256)
void haar_dwt2_kernel(const float* __restrict__ in, float* __restrict__ out) {
    // total threads = B*C*H2*WQ = 8*32*256*64 = 4,194,304
    unsigned t = blockIdx.x * blockDim.x + threadIdx.x;

    unsigned wq = t & (WQ - 1);            // 0..63
    unsigned h2 = (t >> 6) & (H2 - 1);     // 0..255
    unsigned c  = (t >> 14) & (C_DIM - 1); // 0..31
    unsigned b  = t >> 19;                 // 0..7

    // input row base for (b, c, 2*h2, 8*wq)
    size_t in_base = ((size_t)(b * C_DIM + c) * H_DIM + 2u * h2) * W_DIM + 8u * wq;
    const float4* r0 = (const float4*)(in + in_base);
    const float4* r1 = (const float4*)(in + in_base + W_DIM);

    float4 a0 = r0[0];  // row0 cols 0..3
    float4 a1 = r0[1];  // row0 cols 4..7
    float4 b0 = r1[0];  // row1 cols 0..3
    float4 b1 = r1[1];  // row1 cols 4..7

    float ll[4], lh[4], hl[4], hh[4];

    // exact R1 arithmetic order (matches reference associativity -> rel_err 0)
    {
        float x00 = a0.x, x01 = a0.y, x10 = b0.x, x11 = b0.y;
        ll[0] = (x00 + x01 + x10 + x11) * 0.5f;
        lh[0] = (x00 + x01 - x10 - x11) * 0.5f;
        hl[0] = (x00 - x01 + x10 - x11) * 0.5f;
        hh[0] = (x00 - x01 - x10 + x11) * 0.5f;
    }
    {
        float x00 = a0.z, x01 = a0.w, x10 = b0.z, x11 = b0.w;
        ll[1] = (x00 + x01 + x10 + x11) * 0.5f;
        lh[1] = (x00 + x01 - x10 - x11) * 0.5f;
        hl[1] = (x00 - x01 + x10 - x11) * 0.5f;
        hh[1] = (x00 - x01 - x10 + x11) * 0.5f;
    }
    {
        float x00 = a1.x, x01 = a1.y, x10 = b1.x, x11 = b1.y;
        ll[2] = (x00 + x01 + x10 + x11) * 0.5f;
        lh[2] = (x00 + x01 - x10 - x11) * 0.5f;
        hl[2] = (x00 - x01 + x10 - x11) * 0.5f;
        hh[2] = (x00 - x01 - x10 + x11) * 0.5f;
    }
    {
        float x00 = a1.z, x01 = a1.w, x10 = b1.z, x11 = b1.w;
        ll[3] = (x00 + x01 + x10 + x11) * 0.5f;
        lh[3] = (x00 + x01 - x10 - x11) * 0.5f;
        hl[3] = (x00 - x01 + x10 - x11) * 0.5f;
        hh[3] = (x00 - x01 - x10 + x11) * 0.5f;
    }

    // output layout: [B, 4, C, H2, W2]
    float4* o_ll = (float4*)(out + ((size_t)(b * 4 + 0) * C_DIM + c) * (H2 * W2) + h2 * W2 + 4u * wq);
    float4* o_lh = (float4*)(out + ((size_t)(b * 4 + 1) * C_DIM + c) * (H2 * W2) + h2 * W2 + 4u * wq);
    float4* o_hl = (float4*)(out + ((size_t)(b * 4 + 2) * C_DIM + c) * (H2 * W2) + h2 * W2 + 4u * wq);
    float4* o_hh = (float4*)(out + ((size_t)(b * 4 + 3) * C_DIM + c) * (H2 * W2) + h2 * W2 + 4u * wq);

    __stcs(o_ll, make_float4(ll[0], ll[1], ll[2], ll[3]));
    __stcs(o_lh, make_float4(lh[0], lh[1], lh[2], lh[3]));
    __stcs(o_hl, make_float4(hl[0], hl[1], hl[2], hl[3]));
    __stcs(o_hh, make_float4(hh[0], hh[1], hh[2], hh[3]));
}

extern "C" void kernel_launch(void* const* d_in, const int* in_sizes, int n_in,
                              void* d_out, int out_size) {
    const float* in = (const float*)d_in[0];
    float* out = (float*)d_out;
    unsigned total = B_DIM * C_DIM * H2 * WQ;   // 4,194,304 threads
    haar_dwt2_kernel<<<total / 256, 256>>>(in, out);
}